// round 11
// baseline (speedup 1.0000x reference)
#include <cuda_runtime.h>
#include <cmath>

#define NUM_S 7
#define NUM_R 6

struct KParams {
    float Z[NUM_S][NUM_R];   // bessel zeros
    float C[NUM_S][NUM_R];   // BNORM * cutoff^-1.5
    float CK[NUM_S][NUM_S];  // sph-harm K(l,m) (* sqrt2 for m>0)
};

// ---------------- host-side constant computation (pure CPU, double) ----------------
static double sph_jn_d(int n, double x) {
    double j0 = sin(x) / x;
    if (n == 0) return j0;
    double j1 = sin(x) / (x * x) - cos(x) / x;
    double jm1 = j0, jc = j1;
    for (int l = 1; l < n; l++) {
        double t = (2.0 * l + 1.0) / x * jc - jm1;
        jm1 = jc; jc = t;
    }
    return jc;
}

static KParams compute_consts() {
    const double PI = 3.14159265358979323846;
    double Z[NUM_S][NUM_R];
    double points[NUM_S + NUM_R];
    for (int k = 0; k < NUM_R; k++) Z[0][k] = (k + 1) * PI;
    int npts = NUM_R + NUM_S - 1;
    for (int i = 0; i < npts; i++) points[i] = (i + 1) * PI;
    double racines[NUM_S + NUM_R];
    for (int order = 1; order < NUM_S; order++) {
        int nroots = NUM_R + NUM_S - 1 - order;
        for (int j = 0; j < nroots; j++) {
            double a = points[j], b = points[j + 1];
            double fa = sph_jn_d(order, a);
            for (int it = 0; it < 80; it++) {
                double m = 0.5 * (a + b);
                double fm = sph_jn_d(order, m);
                if (fa * fm <= 0.0) b = m; else { a = m; fa = fm; }
            }
            racines[j] = 0.5 * (a + b);
        }
        for (int i = 0; i < nroots; i++) points[i] = racines[i];
        for (int k = 0; k < NUM_R; k++) Z[order][k] = racines[k];
    }
    KParams h;
    double norm_const = pow(1.0 / 5.0, 1.5);
    for (int l = 0; l < NUM_S; l++)
        for (int j = 0; j < NUM_R; j++) {
            double bn = 1.0 / sqrt(0.5 * sph_jn_d(l + 1, Z[l][j]) * sph_jn_d(l + 1, Z[l][j]));
            h.Z[l][j] = (float)Z[l][j];
            h.C[l][j] = (float)(bn * norm_const);
        }
    double fact[16]; fact[0] = 1.0;
    for (int i = 1; i < 16; i++) fact[i] = fact[i - 1] * i;
    for (int l = 0; l < NUM_S; l++)
        for (int m = 0; m <= l; m++) {
            double K = sqrt((2.0 * l + 1.0) / (4.0 * PI) * fact[l - m] / fact[l + m]);
            if (m > 0) K *= sqrt(2.0);
            h.CK[l][m] = (float)K;
        }
    return h;
}

static const KParams& host_consts() {
    static KParams h = compute_consts();
    return h;
}

// ---------------- fast branch-free sincos, valid for x in [0, ~100] ----------------
__device__ __forceinline__ void fast_sincos(float x, float& so, float& co) {
    float kf = rintf(x * 0.63661977236758134f);          // x * 2/pi
    int   qi = (int)kf;
    float r  = fmaf(kf, -1.5707962513f, x);              // PIO2_HI
    r        = fmaf(kf, -7.54978942e-8f, r);             // PIO2_LO
    float r2 = r * r;
    float ps = fmaf(r2, fmaf(r2, -1.9515295891e-4f, 8.3321608736e-3f), -1.6666654611e-1f);
    ps = fmaf(r * r2, ps, r);
    float pc = fmaf(r2, fmaf(r2, fmaf(r2, 2.443315711809948e-5f, -1.388731625493765e-3f),
                             4.166664568298827e-2f), -0.5f);
    pc = fmaf(r2, pc, 1.0f);
    bool swap = qi & 1;
    float ss = swap ? pc : ps;
    float cc = swap ? ps : pc;
    if ((qi >> 1) & 1) ss = -ss;
    if (((qi + 1) >> 1) & 1) cc = -cc;
    so = ss; co = cc;
}

// ---------------- single fused kernel ----------------
#define TPB 256                                // 8 warps
#define QPB 64                                 // quads per block
#define RBF_ROW 42                             // rbf row: l*6+j
// smem: rbf[64][42] + sph[64][49] + tab2[147](int2) + d[64] + u[64] ~= 24.4 KB
#define K_SMEM (QPB * RBF_ROW * 4 + QPB * 49 * 4 + 147 * 8 + QPB * 4 + QPB * 4)

__global__ __launch_bounds__(TPB, 8)
void fused_kernel(const float* __restrict__ D,
                  const float* __restrict__ Alpha, const float* __restrict__ Theta,
                  const int* __restrict__ id4, float* __restrict__ out,
                  int NQ, KParams P) {
    extern __shared__ __align__(16) float smem[];
    float* rbf_s = smem;                           // [QPB][42]
    float* sph_s = rbf_s + QPB * RBF_ROW;          // [QPB][49]
    int2*  tab2_s = (int2*)(sph_s + QPB * 49);     // [147] packed pair descriptors
    float* d_s   = (float*)(tab2_s + 147);         // [QPB]
    float* u_s   = d_s + QPB;                      // [QPB]

    int t = threadIdx.x;
    int q0 = blockIdx.x * QPB;
    int nq = min(QPB, NQ - q0);

    // phase 0: per-quad distance + envelope; pair decode table
    if (t < nq) {
        int e = __ldg(id4 + q0 + t);
        float d = __ldg(D + e) * 0.2f;             // D / CUTOFF
        float invd = 1.0f / d;
        float d2 = d * d, d4 = d2 * d2, d5 = d4 * d;
        float u = invd + d5 * (-28.0f + d * (48.0f - 21.0f * d));
        if (!(d < 1.0f)) u = 0.0f;
        d_s[t] = d;
        u_s[t] = u;
    }
    if (t < 147) {
        // float4 element f = t of a quad-PAIR row covers float2 elements 2f, 2f+1
        int pk[2];
#pragma unroll
        for (int h = 0; h < 2; h++) {
            int g = 2 * t + h;                 // 0..293
            int p = (g >= 147) ? 1 : 0;        // quad parity within pair
            int r = g - 147 * p;               // float2 index in quad row
            int c = r / 3;                     // sph column 0..48
            int w = r - c * 3;                 // float2 within 6-float group
            int l = (c >= 1) + (c >= 4) + (c >= 9) + (c >= 16) + (c >= 25) + (c >= 36);
            pk[h] = ((p * 49 + c) << 8) | (p * RBF_ROW + l * 6 + w * 2);
        }
        tab2_s[t] = make_int2(pk[0], pk[1]);
    }
    __syncthreads();

    // phase A: fused rbf + sph compute.
    if (t < 192) {
        for (int i = t; i < nq * 6; i += 192) {
            int q = i / 6, j = i - q * 6;
            float d = d_s[q];
            float uc = u_s[q];
            float* rrow = rbf_s + q * RBF_ROW + j;
#pragma unroll
            for (int l = 0; l < NUM_S; l++) {
                float x = d * P.Z[l][j];
                float s, c;
                fast_sincos(x, s, c);
                float invx = 1.0f / x;
                float cur = s * invx;                      // j0
                if (l >= 1) {
                    float prev = cur;
                    cur = s * invx * invx - c * invx;      // j1 (same form as reference)
#pragma unroll
                    for (int k = 1; k < l; k++) {
                        float nx = (2.0f * k + 1.0f) * invx * cur - prev;
                        prev = cur; cur = nx;
                    }
                }
                rrow[l * 6] = uc * P.C[l][j] * cur;
            }
        }
    } else {
        int q = t - 192;
        if (q < nq) {
            float th = __ldg(Alpha + q0 + q), ph = __ldg(Theta + q0 + q);
            float st_, ct_;
            fast_sincos(th, st_, ct_);
            float* sp = sph_s + q * 49;
            float pmm = 1.0f;
#pragma unroll
            for (int m = 0; m < NUM_S; m++) {
                float cm, sm;
                if (m == 0) { cm = 1.0f; sm = 0.0f; }
                else fast_sincos((float)m * ph, sm, cm);
                float pa = pmm;
                {   // l = m
                    int l = m;
                    float k = P.CK[l][m];
                    if (m == 0) sp[l * l] = k * pa;
                    else { sp[l * l + m] = k * cm * pa; sp[(l + 1) * (l + 1) - m] = k * sm * pa; }
                }
                if (m < NUM_S - 1) {
                    float pb = (2.0f * m + 1.0f) * ct_ * pa;
                    {   // l = m+1
                        int l = m + 1;
                        float k = P.CK[l][m];
                        if (m == 0) sp[l * l] = k * pb;
                        else { sp[l * l + m] = k * cm * pb; sp[(l + 1) * (l + 1) - m] = k * sm * pb; }
                    }
#pragma unroll
                    for (int l = m + 2; l < NUM_S; l++) {
                        float pc = ((2.0f * l - 1.0f) * ct_ * pb - (float)(l + m - 1) * pa)
                                   * (1.0f / (float)(l - m));
                        pa = pb; pb = pc;
                        float k = P.CK[l][m];
                        if (m == 0) sp[l * l] = k * pc;
                        else { sp[l * l + m] = k * cm * pc; sp[(l + 1) * (l + 1) - m] = k * sm * pc; }
                    }
                }
                pmm = (1.0f - 2.0f * (m + 1)) * st_ * pmm;
            }
        }
    }
    __syncthreads();

    // phase B: warp-per-quad-PAIR. Pair row = 294 float2 = 147 float4 (16B
    // aligned, stride 2352B). Lane L writes float4 elements {L, L+32, ...}.
    // Warp round = 512 contiguous bytes; no per-element division; table LDS
    // is loop-invariant across pairs (hoistable).
    {
        int warp = t >> 5, lane = t & 31;
        int np = nq >> 1;
        for (int pi = warp; pi < np; pi += 8) {
            int qa = pi << 1;
            const float* sq = sph_s + qa * 49;
            const float* rq = rbf_s + qa * RBF_ROW;
            float4* op = (float4*)(out + (size_t)(q0 + qa) * 294);
#pragma unroll
            for (int k = 0; k < 5; k++) {
                int f = lane + 32 * k;
                if (k < 4 || f < 147) {
                    int2 pk = tab2_s[f];
                    float  s0 = sq[pk.x >> 8];
                    float2 v0 = *(const float2*)(rq + (pk.x & 255));
                    float  s1 = sq[pk.y >> 8];
                    float2 v1 = *(const float2*)(rq + (pk.y & 255));
                    __stcs(op + f, make_float4(s0 * v0.x, s0 * v0.y, s1 * v1.x, s1 * v1.y));
                }
            }
        }
        // odd tail quad (never taken for NQ % QPB == 0 shapes)
        if (nq & 1) {
            int q = nq - 1;
            if (warp == 0) {
                const float* sq = sph_s + q * 49;
                const float* rq = rbf_s + q * RBF_ROW;
                float2* oq = (float2*)(out + (size_t)(q0 + q) * 294);
                for (int r = lane; r < 147; r += 32) {
                    int c = r / 3, w = r - c * 3;
                    int l = (c >= 1) + (c >= 4) + (c >= 9) + (c >= 16) + (c >= 25) + (c >= 36);
                    float s = sq[c];
                    float2 v = *(const float2*)(rq + l * 6 + w * 2);
                    __stcs(oq + r, make_float2(s * v.x, s * v.y));
                }
            }
        }
    }
}

extern "C" void kernel_launch(void* const* d_in, const int* in_sizes, int n_in,
                              void* d_out, int out_size) {
    const float* D   = (const float*)d_in[0];
    const float* Al  = (const float*)d_in[1];
    const float* Th  = (const float*)d_in[2];
    const int*   id4 = (const int*)d_in[3];
    float* out = (float*)d_out;
    int NQ = in_sizes[1];

    const KParams& H = host_consts();

    cudaFuncSetAttribute(fused_kernel, cudaFuncAttributeMaxDynamicSharedMemorySize, K_SMEM);

    fused_kernel<<<(NQ + QPB - 1) / QPB, TPB, K_SMEM>>>(D, Al, Th, id4, out, NQ, H);
}

// round 12
// speedup vs baseline: 1.0211x; 1.0211x over previous
#include <cuda_runtime.h>
#include <cmath>

#define NUM_S 7
#define NUM_R 6

struct KParams {
    float Z[NUM_S][NUM_R];   // bessel zeros
    float C[NUM_S][NUM_R];   // BNORM * cutoff^-1.5
    float CK[NUM_S][NUM_S];  // sph-harm K(l,m) (* sqrt2 for m>0)
};

// ---------------- host-side constant computation (pure CPU, double) ----------------
static double sph_jn_d(int n, double x) {
    double j0 = sin(x) / x;
    if (n == 0) return j0;
    double j1 = sin(x) / (x * x) - cos(x) / x;
    double jm1 = j0, jc = j1;
    for (int l = 1; l < n; l++) {
        double t = (2.0 * l + 1.0) / x * jc - jm1;
        jm1 = jc; jc = t;
    }
    return jc;
}

static KParams compute_consts() {
    const double PI = 3.14159265358979323846;
    double Z[NUM_S][NUM_R];
    double points[NUM_S + NUM_R];
    for (int k = 0; k < NUM_R; k++) Z[0][k] = (k + 1) * PI;
    int npts = NUM_R + NUM_S - 1;
    for (int i = 0; i < npts; i++) points[i] = (i + 1) * PI;
    double racines[NUM_S + NUM_R];
    for (int order = 1; order < NUM_S; order++) {
        int nroots = NUM_R + NUM_S - 1 - order;
        for (int j = 0; j < nroots; j++) {
            double a = points[j], b = points[j + 1];
            double fa = sph_jn_d(order, a);
            for (int it = 0; it < 80; it++) {
                double m = 0.5 * (a + b);
                double fm = sph_jn_d(order, m);
                if (fa * fm <= 0.0) b = m; else { a = m; fa = fm; }
            }
            racines[j] = 0.5 * (a + b);
        }
        for (int i = 0; i < nroots; i++) points[i] = racines[i];
        for (int k = 0; k < NUM_R; k++) Z[order][k] = racines[k];
    }
    KParams h;
    double norm_const = pow(1.0 / 5.0, 1.5);
    for (int l = 0; l < NUM_S; l++)
        for (int j = 0; j < NUM_R; j++) {
            double bn = 1.0 / sqrt(0.5 * sph_jn_d(l + 1, Z[l][j]) * sph_jn_d(l + 1, Z[l][j]));
            h.Z[l][j] = (float)Z[l][j];
            h.C[l][j] = (float)(bn * norm_const);
        }
    double fact[16]; fact[0] = 1.0;
    for (int i = 1; i < 16; i++) fact[i] = fact[i - 1] * i;
    for (int l = 0; l < NUM_S; l++)
        for (int m = 0; m <= l; m++) {
            double K = sqrt((2.0 * l + 1.0) / (4.0 * PI) * fact[l - m] / fact[l + m]);
            if (m > 0) K *= sqrt(2.0);
            h.CK[l][m] = (float)K;
        }
    return h;
}

static const KParams& host_consts() {
    static KParams h = compute_consts();
    return h;
}

// ---------------- fast branch-free sincos, valid for x in [0, ~100] ----------------
__device__ __forceinline__ void fast_sincos(float x, float& so, float& co) {
    float kf = rintf(x * 0.63661977236758134f);          // x * 2/pi
    int   qi = (int)kf;
    float r  = fmaf(kf, -1.5707962513f, x);              // PIO2_HI
    r        = fmaf(kf, -7.54978942e-8f, r);             // PIO2_LO
    float r2 = r * r;
    float ps = fmaf(r2, fmaf(r2, -1.9515295891e-4f, 8.3321608736e-3f), -1.6666654611e-1f);
    ps = fmaf(r * r2, ps, r);
    float pc = fmaf(r2, fmaf(r2, fmaf(r2, 2.443315711809948e-5f, -1.388731625493765e-3f),
                             4.166664568298827e-2f), -0.5f);
    pc = fmaf(r2, pc, 1.0f);
    bool swap = qi & 1;
    float ss = swap ? pc : ps;
    float cc = swap ? ps : pc;
    if ((qi >> 1) & 1) ss = -ss;
    if (((qi + 1) >> 1) & 1) cc = -cc;
    so = ss; co = cc;
}

// ---------------- single fused kernel ----------------
#define TPB 256                                // 8 warps
#define QPB 64                                 // quads per block
#define RBF_ROW 42                             // rbf row: l*6+j
#define K_SMEM (QPB * RBF_ROW * 4 + QPB * 49 * 4 + 148 * 4 + QPB * 4 + QPB * 4)

__global__ __launch_bounds__(TPB, 8)
void fused_kernel(const float* __restrict__ D,
                  const float* __restrict__ Alpha, const float* __restrict__ Theta,
                  const int* __restrict__ id4, float* __restrict__ out,
                  int NQ, KParams P) {
    extern __shared__ __align__(16) float smem[];
    float* rbf_s = smem;                           // [QPB][42]
    float* sph_s = rbf_s + QPB * RBF_ROW;          // [QPB][49]
    int*   tab_s = (int*)(sph_s + QPB * 49);       // [147] packed (c<<8)|wordoff
    float* d_s   = (float*)(tab_s + 148);          // [QPB]
    float* u_s   = d_s + QPB;                      // [QPB]

    int t = threadIdx.x;
    int q0 = blockIdx.x * QPB;
    int nq = min(QPB, NQ - q0);

    // phase 0: per-quad distance + envelope; decode table
    if (t < nq) {
        int e = __ldg(id4 + q0 + t);
        float d = __ldg(D + e) * 0.2f;             // D / CUTOFF
        float invd = 1.0f / d;
        float d2 = d * d, d4 = d2 * d2, d5 = d4 * d;
        float u = invd + d5 * (-28.0f + d * (48.0f - 21.0f * d));
        if (!(d < 1.0f)) u = 0.0f;
        d_s[t] = d;
        u_s[t] = u;
    }
    if (t < 147) {
        int c = t / 3;                 // sph-harm column 0..48
        int w = t - c * 3;             // float2 within 6-float group
        int l = (c >= 1) + (c >= 4) + (c >= 9) + (c >= 16) + (c >= 25) + (c >= 36); // LIDX[c]
        tab_s[t] = (c << 8) | (l * 6 + w * 2);
    }
    __syncthreads();

    // phase A: fused rbf + sph compute.
    if (t < 192) {
        for (int i = t; i < nq * 6; i += 192) {
            int q = i / 6, j = i - q * 6;
            float d = d_s[q];
            float uc = u_s[q];
            float* rrow = rbf_s + q * RBF_ROW + j;
#pragma unroll
            for (int l = 0; l < NUM_S; l++) {
                float x = d * P.Z[l][j];
                float s, c;
                fast_sincos(x, s, c);
                float invx = 1.0f / x;
                float cur = s * invx;                      // j0
                if (l >= 1) {
                    float prev = cur;
                    cur = s * invx * invx - c * invx;      // j1 (same form as reference)
#pragma unroll
                    for (int k = 1; k < l; k++) {
                        float nx = (2.0f * k + 1.0f) * invx * cur - prev;
                        prev = cur; cur = nx;
                    }
                }
                rrow[l * 6] = uc * P.C[l][j] * cur;
            }
        }
    } else {
        int q = t - 192;
        if (q < nq) {
            float th = __ldg(Alpha + q0 + q), ph = __ldg(Theta + q0 + q);
            float st_, ct_;
            fast_sincos(th, st_, ct_);
            float* sp = sph_s + q * 49;
            float pmm = 1.0f;
#pragma unroll
            for (int m = 0; m < NUM_S; m++) {
                float cm, sm;
                if (m == 0) { cm = 1.0f; sm = 0.0f; }
                else fast_sincos((float)m * ph, sm, cm);
                float pa = pmm;
                {   // l = m
                    int l = m;
                    float k = P.CK[l][m];
                    if (m == 0) sp[l * l] = k * pa;
                    else { sp[l * l + m] = k * cm * pa; sp[(l + 1) * (l + 1) - m] = k * sm * pa; }
                }
                if (m < NUM_S - 1) {
                    float pb = (2.0f * m + 1.0f) * ct_ * pa;
                    {   // l = m+1
                        int l = m + 1;
                        float k = P.CK[l][m];
                        if (m == 0) sp[l * l] = k * pb;
                        else { sp[l * l + m] = k * cm * pb; sp[(l + 1) * (l + 1) - m] = k * sm * pb; }
                    }
#pragma unroll
                    for (int l = m + 2; l < NUM_S; l++) {
                        float pc = ((2.0f * l - 1.0f) * ct_ * pb - (float)(l + m - 1) * pa)
                                   * (1.0f / (float)(l - m));
                        pa = pb; pb = pc;
                        float k = P.CK[l][m];
                        if (m == 0) sp[l * l] = k * pc;
                        else { sp[l * l + m] = k * cm * pc; sp[(l + 1) * (l + 1) - m] = k * sm * pc; }
                    }
                }
                pmm = (1.0f - 2.0f * (m + 1)) * st_ * pmm;
            }
        }
    }
    __syncthreads();

    // phase B: warp-per-quad, decode table HOISTED into registers (loop-
    // invariant across the warp's quads; removes 1 of 3 LDS per element).
    // Lane L writes float2 elements {L, L+32, ..., L+128} of the quad's
    // 147-float2 row: each warp round = 256 contiguous bytes.
    {
        int warp = t >> 5, lane = t & 31;
        int pk0 = tab_s[lane];
        int pk1 = tab_s[lane + 32];
        int pk2 = tab_s[lane + 64];
        int pk3 = tab_s[lane + 96];
        int pk4 = (lane < 19) ? tab_s[lane + 128] : 0;
        float2* ob2 = (float2*)(out + (size_t)q0 * 294);
        for (int q = warp; q < nq; q += 8) {
            const float* sq = sph_s + q * 49;
            const float* rq = rbf_s + q * RBF_ROW;
            float2* oq = ob2 + q * 147;
            {
                float s = sq[pk0 >> 8];
                float2 v = *(const float2*)(rq + (pk0 & 255));
                __stcs(oq + lane, make_float2(s * v.x, s * v.y));
            }
            {
                float s = sq[pk1 >> 8];
                float2 v = *(const float2*)(rq + (pk1 & 255));
                __stcs(oq + lane + 32, make_float2(s * v.x, s * v.y));
            }
            {
                float s = sq[pk2 >> 8];
                float2 v = *(const float2*)(rq + (pk2 & 255));
                __stcs(oq + lane + 64, make_float2(s * v.x, s * v.y));
            }
            {
                float s = sq[pk3 >> 8];
                float2 v = *(const float2*)(rq + (pk3 & 255));
                __stcs(oq + lane + 96, make_float2(s * v.x, s * v.y));
            }
            if (lane < 19) {
                float s = sq[pk4 >> 8];
                float2 v = *(const float2*)(rq + (pk4 & 255));
                __stcs(oq + lane + 128, make_float2(s * v.x, s * v.y));
            }
        }
    }
}

extern "C" void kernel_launch(void* const* d_in, const int* in_sizes, int n_in,
                              void* d_out, int out_size) {
    const float* D   = (const float*)d_in[0];
    const float* Al  = (const float*)d_in[1];
    const float* Th  = (const float*)d_in[2];
    const int*   id4 = (const int*)d_in[3];
    float* out = (float*)d_out;
    int NQ = in_sizes[1];

    const KParams& H = host_consts();

    cudaFuncSetAttribute(fused_kernel, cudaFuncAttributeMaxDynamicSharedMemorySize, K_SMEM);

    fused_kernel<<<(NQ + QPB - 1) / QPB, TPB, K_SMEM>>>(D, Al, Th, id4, out, NQ, H);
}